// round 13
// baseline (speedup 1.0000x reference)
#include <cuda_runtime.h>
#include <cuda_fp16.h>
#include <cstdint>

#define DEV __device__ __forceinline__

constexpr int Bn    = 65536;   // batch
constexpr int Hh    = 64;      // hidden
constexpr int Gg    = 192;     // 3*H
constexpr int Kf    = 1024;    // T*H
constexpr int Tt    = 16;      // type count
constexpr int TILES = 17;      // 16 register tiles + 1 c tile (64 k each)
constexpr int WTILE_BYTES = Gg * 128;   // 192 rows x 128B (64 fp16) = 24576

// ---- device-global scratch (no allocations allowed) ----
__device__ float g_hidden[(size_t)Bn * Hh];                       // stage A output
__device__ __align__(16) unsigned char g_Wq[TILES * WTILE_BYTES]; // stage B W fp16, tile-swizzled
__device__ __align__(16) unsigned char g_WA[Tt * 2 * WTILE_BYTES];// stage A W bank: phase0=Whh, 1=Wih

extern __shared__ __align__(1024) char dynsm[];

DEV float sigm(float v) { return 1.0f / (1.0f + __expf(-v)); }

DEV uint32_t smem_u32(const void* p) {
    uint32_t a;
    asm("{ .reg .u64 t; cvta.to.shared.u64 t, %1; cvt.u32.u64 %0, t; }" : "=r"(a) : "l"(p));
    return a;
}
DEV uint32_t sw128(uint32_t off) { return off ^ ((off >> 3) & 0x70); }

DEV void ldsm4(uint32_t* r, uint32_t addr) {
    asm volatile("ldmatrix.sync.aligned.m8n8.x4.shared.b16 {%0,%1,%2,%3}, [%4];"
        : "=r"(r[0]), "=r"(r[1]), "=r"(r[2]), "=r"(r[3]) : "r"(addr));
}
DEV void mma_f16(float* d, const uint32_t* a, const uint32_t* b) {
    asm volatile(
        "mma.sync.aligned.m16n8k16.row.col.f32.f16.f16.f32 "
        "{%0,%1,%2,%3}, {%4,%5,%6,%7}, {%8,%9}, {%0,%1,%2,%3};"
        : "+f"(d[0]), "+f"(d[1]), "+f"(d[2]), "+f"(d[3])
        : "r"(a[0]), "r"(a[1]), "r"(a[2]), "r"(a[3]), "r"(b[0]), "r"(b[1]));
}
DEV void cp16(uint32_t smem, const void* g) {
    asm volatile("cp.async.cg.shared.global [%0], [%1], 16;" :: "r"(smem), "l"(g));
}
DEV void cp_commit() { asm volatile("cp.async.commit_group;" ::: "memory"); }
DEV void cp_wait0()  { asm volatile("cp.async.wait_group 0;" ::: "memory"); }

DEV uint32_t packh2(float a, float b) {
    __half2 h = __floats2half2_rn(a, b);
    return *reinterpret_cast<uint32_t*>(&h);
}

// ---------------------------------------------------------------------------
// buildA / buildB: weights -> fp16 SW128 tiles (W loads become raw cp.async)
// ---------------------------------------------------------------------------
__global__ void buildA_kernel(const float* __restrict__ Wih, const float* __restrict__ Whh) {
    int idx = blockIdx.x * 256 + threadIdx.x;
    if (idx >= Tt * 2 * Gg * 64) return;
    int t   = idx / (2 * Gg * 64);
    int rem = idx - t * (2 * Gg * 64);
    int p   = rem / (Gg * 64);
    int r2  = rem - p * (Gg * 64);
    int r   = r2 >> 6;
    int kk  = r2 & 63;
    const float* src = (p == 0) ? Whh : Wih;
    float val = src[((size_t)t * Gg + r) * 64 + kk];
    uint32_t off = sw128((uint32_t)(r * 128 + kk * 2));
    *(__half*)(g_WA + (size_t)(t * 2 + p) * WTILE_BYTES + off) = __float2half_rn(val);
}

__global__ void buildB_kernel(const float* __restrict__ cWih, const float* __restrict__ cWhh) {
    int idx = blockIdx.x * 256 + threadIdx.x;
    if (idx >= TILES * Gg * 64) return;
    int t   = idx / (Gg * 64);
    int rem = idx - t * (Gg * 64);
    int r   = rem >> 6;
    int kk  = rem & 63;
    int k   = t * 64 + kk;
    float val = (k < Kf) ? cWih[(size_t)r * Kf + k] : cWhh[r * Hh + (k - Kf)];
    uint32_t off = sw128((uint32_t)(r * 128 + kk * 2));
    *(__half*)(g_Wq + (size_t)t * WTILE_BYTES + off) = __float2half_rn(val);
}

// ---------------------------------------------------------------------------
// Stage A (mma, single-pass fp16): unchanged from R11 (passing, ~55us).
// ---------------------------------------------------------------------------
constexpr int A_W0 = 0;
constexpr int A_W1 = 24576;
constexpr int A_A0 = 49152;
constexpr int A_A1 = 57344;
constexpr int A_HN = 65536;
constexpr int A_DS = 81920;
constexpr int SMEMA_BYTES = 107520;

__global__ void __launch_bounds__(256, 2)
stageA_mma(const float* __restrict__ x, const int* __restrict__ typ,
           const float* __restrict__ regs,
           const float* __restrict__ bih, const float* __restrict__ bhh)
{
    char* sm = dynsm;
    const uint32_t sb = smem_u32(sm);
    __shared__ int list[1024];
    __shared__ int pcnt;

    const int tid = threadIdx.x;
    const int wid = tid >> 5, lane = tid & 31;
    const int t   = blockIdx.y;
    const int c0  = blockIdx.x * 1024;

    if (tid == 0) pcnt = 0;
    __syncthreads();
    for (int i = tid; i < 1024; i += 256) {
        if (typ[c0 + i] == t) list[atomicAdd(&pcnt, 1)] = c0 + i;
    }
    __syncthreads();
    const int n = pcnt;
    if (n == 0) return;

    {
        const unsigned char* w0 = g_WA + (size_t)(t * 2 + 0) * WTILE_BYTES;
        const unsigned char* w1 = g_WA + (size_t)(t * 2 + 1) * WTILE_BYTES;
        #pragma unroll
        for (int j = 0; j < 6; j++) {
            int i = (tid + j * 256) * 16;
            cp16(sb + A_W0 + i, w0 + i);
            cp16(sb + A_W1 + i, w1 + i);
        }
        cp_commit();
    }

    const int h  = tid & 63;
    const int rl = tid >> 6;
    const float bR  = bih[t * Gg + h]        + bhh[t * Gg + h];
    const float bZ  = bih[t * Gg + 64 + h]   + bhh[t * Gg + 64 + h];
    const float bN  = bih[t * Gg + 128 + h];
    const float bHN = bhh[t * Gg + 128 + h];

    const int arow = tid >> 2;
    const int aqd  = tid & 3;

    const int l8 = lane & 7, li = lane >> 3;
    const int am_off = (li & 1) * 8, ak_off = (li >> 1) * 8;
    const int wn_off = (li >> 1) * 8, wk_off = (li & 1) * 8;
    const int wm = wid & 1;
    const int wn = wid >> 1;

    float* Hn = (float*)(sm + A_HN);
    float* Ds = (float*)(sm + A_DS);

    bool firstGroup = true;
    for (int base = 0; base < n; base += 64) {
        const int m = (n - base < 64) ? (n - base) : 64;

        int gj = base + arow; if (gj > n - 1) gj = n - 1;
        const int gb = list[gj];

        {
            const float* rrow = regs + (size_t)gb * Kf + t * 64;
            const float* xrow = x + (size_t)gb * 64;
            float fr[16], fx[16];
            #pragma unroll
            for (int i = 0; i < 4; i++) {
                float4 vr = *(const float4*)(rrow + aqd * 16 + i * 4);
                float4 vx = *(const float4*)(xrow + aqd * 16 + i * 4);
                fr[4*i] = vr.x; fr[4*i+1] = vr.y; fr[4*i+2] = vr.z; fr[4*i+3] = vr.w;
                fx[4*i] = vx.x; fx[4*i+1] = vx.y; fx[4*i+2] = vx.z; fx[4*i+3] = vx.w;
            }
            uint32_t hr[8], hx[8];
            #pragma unroll
            for (int i = 0; i < 8; i++) {
                hr[i] = packh2(fr[2*i], fr[2*i+1]);
                hx[i] = packh2(fx[2*i], fx[2*i+1]);
            }
            uint32_t bo = (uint32_t)(arow * 128 + aqd * 32);
            uint32_t o0 = sw128(bo), o1 = sw128(bo + 16);
            *(uint4*)(sm + A_A0 + o0) = make_uint4(hr[0], hr[1], hr[2], hr[3]);
            *(uint4*)(sm + A_A0 + o1) = make_uint4(hr[4], hr[5], hr[6], hr[7]);
            *(uint4*)(sm + A_A1 + o0) = make_uint4(hx[0], hx[1], hx[2], hx[3]);
            *(uint4*)(sm + A_A1 + o1) = make_uint4(hx[4], hx[5], hx[6], hx[7]);
        }
        if (firstGroup) { cp_wait0(); firstGroup = false; }
        __syncthreads();

        float acc[2][6][4];
        #pragma unroll
        for (int a = 0; a < 2; a++)
            #pragma unroll
            for (int b = 0; b < 6; b++)
                #pragma unroll
                for (int r = 0; r < 4; r++) acc[a][b][r] = 0.0f;

        #pragma unroll
        for (int ph = 0; ph < 2; ph++) {
            const uint32_t aB = sb + (ph ? A_A1 : A_A0);
            const uint32_t wB = sb + (ph ? A_W1 : A_W0);
            #pragma unroll
            for (int ks = 0; ks < 4; ks++) {
                const int k0 = ks * 16;
                uint32_t ah[2][4];
                #pragma unroll
                for (int mt = 0; mt < 2; mt++) {
                    int row = wm * 32 + mt * 16 + am_off + l8;
                    ldsm4(ah[mt], aB + sw128((uint32_t)(row * 128 + (k0 + ak_off) * 2)));
                }
                #pragma unroll
                for (int np = 0; np < 3; np++) {
                    int nrow = wn * 48 + np * 16 + wn_off + l8;
                    uint32_t wf[4];
                    ldsm4(wf, wB + sw128((uint32_t)(nrow * 128 + (k0 + wk_off) * 2)));
                    #pragma unroll
                    for (int mt = 0; mt < 2; mt++) {
                        mma_f16(acc[mt][2*np],   ah[mt], wf);
                        mma_f16(acc[mt][2*np+1], ah[mt], wf + 2);
                    }
                }
            }
            if (ph == 0) {
                #pragma unroll
                for (int mt = 0; mt < 2; mt++)
                    #pragma unroll
                    for (int nt = 0; nt < 6; nt++) {
                        int colb = wn * 48 + nt * 8;
                        if (colb >= 128) {
                            #pragma unroll
                            for (int r = 0; r < 4; r++) {
                                int row = wm * 32 + mt * 16 + (lane >> 2) + ((r >> 1) << 3);
                                int col = colb - 128 + ((lane & 3) << 1) + (r & 1);
                                Hn[row * 64 + col] = acc[mt][nt][r];
                            }
                        }
                    }
            }
        }

        #pragma unroll
        for (int half = 0; half < 2; half++) {
            __syncthreads();
            if (wm == half) {
                #pragma unroll
                for (int mt = 0; mt < 2; mt++)
                    #pragma unroll
                    for (int nt = 0; nt < 6; nt++)
                        #pragma unroll
                        for (int r = 0; r < 4; r++) {
                            int lrow = mt * 16 + (lane >> 2) + ((r >> 1) << 3);
                            int col  = wn * 48 + nt * 8 + ((lane & 3) << 1) + (r & 1);
                            Ds[lrow * 200 + col] = acc[mt][nt][r];
                        }
            }
            __syncthreads();
            #pragma unroll 2
            for (int i = 0; i < 8; i++) {
                int lrow = rl + i * 4;
                int rowg = half * 32 + lrow;
                if (rowg < m) {
                    int gbr = list[base + rowg];
                    float ar = Ds[lrow * 200 + h];
                    float az = Ds[lrow * 200 + 64 + h];
                    float an = Ds[lrow * 200 + 128 + h];
                    float hn = Hn[rowg * 64 + h];
                    float rg = regs[(size_t)gbr * Kf + t * 64 + h];
                    float rv = sigm(ar + bR);
                    float zv = sigm(az + bZ);
                    float nv = tanhf(an + bN + rv * bHN + (rv - 1.0f) * hn);
                    g_hidden[(size_t)gbr * 64 + h] = (1.0f - zv) * nv + zv * rg;
                }
            }
        }
        __syncthreads();
    }
}

// ---------------------------------------------------------------------------
// Stage B: single-pass fp16 mma GEMM. M-tile 128, 8 warps 2m x 4n
// (warp tile 64x48), ONE CTA per SM (launch_bounds(256,1): ~170 regs, no
// spills). A prefetched into registers a full tile early (2 rows/thread);
// W double-buffered via cp.async. Tile it=0 -> t=16 (c) for fp16 hn snapshot.
// smem: stage s @ s*40960 {A 16K, W 24K} | Hn fp16 @81920 16K |
//       Ds f32 [128][200] @98304 102400 -> 200704 total.
// ---------------------------------------------------------------------------
constexpr int SBUF  = 40960;
constexpr int SB_HN = 81920;
constexpr int SB_DS = 98304;
constexpr int SMEMB_BYTES = 200704;

__global__ void __launch_bounds__(256, 1)
stageB_mma(const float* __restrict__ regs, const int* __restrict__ typ,
           const float* __restrict__ c,
           const float* __restrict__ cbih, const float* __restrict__ cbhh,
           float* __restrict__ out)
{
    char* sm = dynsm;
    const uint32_t sb = smem_u32(sm);
    __shared__ int styp[128];

    const int tid  = threadIdx.x;
    const int wid  = tid >> 5, lane = tid & 31;
    const int wm   = wid & 1;      // rows wm*64
    const int wn   = wid >> 1;     // cols wn*48
    const int bm   = blockIdx.x * 128;

    if (tid < 128) styp[tid] = typ[bm + tid];
    __syncthreads();

    float acc[4][6][4];
    #pragma unroll
    for (int a = 0; a < 4; a++)
        #pragma unroll
        for (int b = 0; b < 6; b++)
            #pragma unroll
            for (int r = 0; r < 4; r++) acc[a][b][r] = 0.0f;

    const int arow = tid >> 2;      // 0..63 ; thread covers rows arow, arow+64
    const int aqd  = tid & 3;       // 16-float quarter

    float4 pf[8];                   // A prefetch: 2 rows x 16 floats
    auto prefetchA = [&](int t) {
        #pragma unroll
        for (int rr = 0; rr < 2; rr++) {
            const int row = arow + rr * 64;
            const float* srow;
            if (t < Tt) {
                srow = (styp[row] == t)
                         ? (g_hidden + (size_t)(bm + row) * 64)
                         : (regs + (size_t)(bm + row) * Kf + t * 64);
            } else {
                srow = c + (size_t)(bm + row) * 64;
            }
            #pragma unroll
            for (int i = 0; i < 4; i++)
                pf[rr * 4 + i] = *(const float4*)(srow + aqd * 16 + i * 4);
        }
    };
    auto storeA = [&](int buf) {
        #pragma unroll
        for (int rr = 0; rr < 2; rr++) {
            uint32_t hp[8];
            #pragma unroll
            for (int i = 0; i < 4; i++) {
                float4 v = pf[rr * 4 + i];
                hp[2*i]   = packh2(v.x, v.y);
                hp[2*i+1] = packh2(v.z, v.w);
            }
            uint32_t bo = (uint32_t)((arow + rr * 64) * 128 + aqd * 32);
            uint32_t o0 = sw128(bo), o1 = sw128(bo + 16);
            *(uint4*)(sm + buf * SBUF + o0) = make_uint4(hp[0], hp[1], hp[2], hp[3]);
            *(uint4*)(sm + buf * SBUF + o1) = make_uint4(hp[4], hp[5], hp[6], hp[7]);
        }
    };
    auto loadW = [&](int t, int buf) {
        const unsigned char* src = g_Wq + (size_t)t * WTILE_BYTES;
        #pragma unroll
        for (int j = 0; j < 6; j++) {
            int i = (tid + j * 256) * 16;
            cp16(sb + buf * SBUF + 16384 + i, src + i);
        }
    };

    const int l8 = lane & 7, li = lane >> 3;
    const int am_off = (li & 1) * 8, ak_off = (li >> 1) * 8;
    const int wn_off = (li >> 1) * 8, wk_off = (li & 1) * 8;

    __half* Hn = (__half*)(sm + SB_HN);   // [128][64] fp16

    // prologue: tile it=0 (t=16, the c tile) into buf 0
    prefetchA(16);
    loadW(16, 0);
    cp_commit();
    storeA(0);
    prefetchA(0);
    cp_wait0();
    __syncthreads();

    for (int it = 0; it <= 16; it++) {
        const int buf = it & 1, nxt = buf ^ 1;
        if (it < 16) {
            loadW(it, nxt);
            cp_commit();
            storeA(nxt);                 // pf holds A for t = it
            if (it < 15) prefetchA(it + 1);
        }

        const uint32_t aB = sb + buf * SBUF;
        const uint32_t wB = aB + 16384;
        #pragma unroll
        for (int ks = 0; ks < 4; ks++) {
            const int k0 = ks * 16;
            uint32_t wf[3][4];
            #pragma unroll
            for (int np = 0; np < 3; np++) {
                int nrow = wn * 48 + np * 16 + wn_off + l8;
                ldsm4(wf[np], wB + sw128((uint32_t)(nrow * 128 + (k0 + wk_off) * 2)));
            }
            #pragma unroll
            for (int mt = 0; mt < 4; mt++) {
                int row = wm * 64 + mt * 16 + am_off + l8;
                uint32_t ah[4];
                ldsm4(ah, aB + sw128((uint32_t)(row * 128 + (k0 + ak_off) * 2)));
                #pragma unroll
                for (int np = 0; np < 3; np++) {
                    mma_f16(acc[mt][2*np],   ah, wf[np]);
                    mma_f16(acc[mt][2*np+1], ah, wf[np] + 2);
                }
            }
        }

        if (it == 0) {
            // snapshot hn = c @ cWhh_n^T (global cols 128..191), fp16
            #pragma unroll
            for (int mt = 0; mt < 4; mt++)
                #pragma unroll
                for (int nt = 0; nt < 6; nt++) {
                    int colb = wn * 48 + nt * 8;
                    if (colb >= 128) {
                        int row0 = wm * 64 + mt * 16 + (lane >> 2);
                        int col  = colb - 128 + ((lane & 3) << 1);
                        *(uint32_t*)&Hn[row0 * 64 + col] =
                            packh2(acc[mt][nt][0], acc[mt][nt][1]);
                        *(uint32_t*)&Hn[(row0 + 8) * 64 + col] =
                            packh2(acc[mt][nt][2], acc[mt][nt][3]);
                    }
                }
        }
        cp_wait0();
        __syncthreads();
    }

    // ---- epilogue: full Ds dump (dedicated region), then fused GRU ----
    float* Ds = (float*)(sm + SB_DS);     // [128][200]
    #pragma unroll
    for (int mt = 0; mt < 4; mt++)
        #pragma unroll
        for (int nt = 0; nt < 6; nt++)
            #pragma unroll
            for (int r = 0; r < 4; r++) {
                int row = wm * 64 + mt * 16 + (lane >> 2) + ((r >> 1) << 3);
                int col = wn * 48 + nt * 8 + ((lane & 3) << 1) + (r & 1);
                Ds[row * 200 + col] = acc[mt][nt][r];
            }
    __syncthreads();

    const int h  = tid & 63;
    const int rl = tid >> 6;
    const float bR  = cbih[h]       + cbhh[h];
    const float bZ  = cbih[64 + h]  + cbhh[64 + h];
    const float bN  = cbih[128 + h];
    const float bHN = cbhh[128 + h];
    #pragma unroll 4
    for (int i = 0; i < 32; i++) {
        int row = rl + i * 4;
        float ar = Ds[row * 200 + h];
        float az = Ds[row * 200 + 64 + h];
        float an = Ds[row * 200 + 128 + h];
        float hn = __half2float(Hn[row * 64 + h]);
        float cv = c[(size_t)(bm + row) * 64 + h];
        float rv = sigm(ar + bR);
        float zv = sigm(az + bZ);
        float nv = tanhf(an + bN + rv * bHN + (rv - 1.0f) * hn);
        out[(size_t)(bm + row) * 64 + h] = (1.0f - zv) * nv + zv * cv;
    }
}

// ---------------------------------------------------------------------------
extern "C" void kernel_launch(void* const* d_in, const int* in_sizes, int n_in,
                              void* d_out, int out_size)
{
    const float* x    = (const float*)d_in[0];
    const int*   typ  = (const int*)  d_in[1];
    const float* c    = (const float*)d_in[2];
    const float* regs = (const float*)d_in[3];
    const float* Wih  = (const float*)d_in[4];
    const float* Whh  = (const float*)d_in[5];
    const float* bih  = (const float*)d_in[6];
    const float* bhh  = (const float*)d_in[7];
    const float* cWih = (const float*)d_in[8];
    const float* cWhh = (const float*)d_in[9];
    const float* cbih = (const float*)d_in[10];
    const float* cbhh = (const float*)d_in[11];
    float* out = (float*)d_out;

    (void)in_sizes; (void)n_in; (void)out_size;

    cudaFuncSetAttribute(stageA_mma,
                         cudaFuncAttributeMaxDynamicSharedMemorySize, SMEMA_BYTES);
    cudaFuncSetAttribute(stageB_mma,
                         cudaFuncAttributeMaxDynamicSharedMemorySize, SMEMB_BYTES);

    buildA_kernel<<<(Tt * 2 * Gg * 64 + 255) / 256, 256>>>(Wih, Whh);
    stageA_mma<<<dim3(64, 16), 256, SMEMA_BYTES>>>(x, typ, regs, bih, bhh);
    buildB_kernel<<<(TILES * Gg * 64 + 255) / 256, 256>>>(cWih, cWhh);
    stageB_mma<<<Bn / 128, 256, SMEMB_BYTES>>>(regs, typ, c, cbih, cbhh, out);
}

// round 14
// speedup vs baseline: 1.3931x; 1.3931x over previous
#include <cuda_runtime.h>
#include <cuda_fp16.h>
#include <cstdint>

#define DEV __device__ __forceinline__

constexpr int Bn    = 65536;   // batch
constexpr int Hh    = 64;      // hidden
constexpr int Gg    = 192;     // 3*H
constexpr int Kf    = 1024;    // T*H
constexpr int Tt    = 16;      // type count
constexpr int TILES = 17;      // 16 register tiles + 1 c tile (64 k each)
constexpr int WTILE_BYTES = Gg * 128;   // 192 rows x 128B (64 fp16) = 24576
constexpr int CHUNK = 2048;    // stage A batch chunk per block

// ---- device-global scratch (no allocations allowed) ----
__device__ float g_hidden[(size_t)Bn * Hh];                       // stage A output
__device__ __align__(16) unsigned char g_Wq[TILES * WTILE_BYTES]; // stage B W fp16, tile-swizzled
__device__ __align__(16) unsigned char g_WA[Tt * 2 * WTILE_BYTES];// stage A W bank: phase0=Whh, 1=Wih

extern __shared__ __align__(1024) char dynsm[];

DEV float sigm(float v) { return 1.0f / (1.0f + __expf(-v)); }

DEV uint32_t smem_u32(const void* p) {
    uint32_t a;
    asm("{ .reg .u64 t; cvta.to.shared.u64 t, %1; cvt.u32.u64 %0, t; }" : "=r"(a) : "l"(p));
    return a;
}
DEV uint32_t sw128(uint32_t off) { return off ^ ((off >> 3) & 0x70); }

DEV void ldsm4(uint32_t* r, uint32_t addr) {
    asm volatile("ldmatrix.sync.aligned.m8n8.x4.shared.b16 {%0,%1,%2,%3}, [%4];"
        : "=r"(r[0]), "=r"(r[1]), "=r"(r[2]), "=r"(r[3]) : "r"(addr));
}
DEV void mma_f16(float* d, const uint32_t* a, const uint32_t* b) {
    asm volatile(
        "mma.sync.aligned.m16n8k16.row.col.f32.f16.f16.f32 "
        "{%0,%1,%2,%3}, {%4,%5,%6,%7}, {%8,%9}, {%0,%1,%2,%3};"
        : "+f"(d[0]), "+f"(d[1]), "+f"(d[2]), "+f"(d[3])
        : "r"(a[0]), "r"(a[1]), "r"(a[2]), "r"(a[3]), "r"(b[0]), "r"(b[1]));
}
DEV void cp16(uint32_t smem, const void* g) {
    asm volatile("cp.async.cg.shared.global [%0], [%1], 16;" :: "r"(smem), "l"(g));
}
DEV void cp_commit() { asm volatile("cp.async.commit_group;" ::: "memory"); }
DEV void cp_wait0()  { asm volatile("cp.async.wait_group 0;" ::: "memory"); }

DEV uint32_t packh2(float a, float b) {
    __half2 h = __floats2half2_rn(a, b);
    return *reinterpret_cast<uint32_t*>(&h);
}

// ---------------------------------------------------------------------------
// buildA / buildB: weights -> fp16 SW128 tiles (W loads become raw cp.async)
// ---------------------------------------------------------------------------
__global__ void buildA_kernel(const float* __restrict__ Wih, const float* __restrict__ Whh) {
    int idx = blockIdx.x * 256 + threadIdx.x;
    if (idx >= Tt * 2 * Gg * 64) return;
    int t   = idx / (2 * Gg * 64);
    int rem = idx - t * (2 * Gg * 64);
    int p   = rem / (Gg * 64);
    int r2  = rem - p * (Gg * 64);
    int r   = r2 >> 6;
    int kk  = r2 & 63;
    const float* src = (p == 0) ? Whh : Wih;
    float val = src[((size_t)t * Gg + r) * 64 + kk];
    uint32_t off = sw128((uint32_t)(r * 128 + kk * 2));
    *(__half*)(g_WA + (size_t)(t * 2 + p) * WTILE_BYTES + off) = __float2half_rn(val);
}

__global__ void buildB_kernel(const float* __restrict__ cWih, const float* __restrict__ cWhh) {
    int idx = blockIdx.x * 256 + threadIdx.x;
    if (idx >= TILES * Gg * 64) return;
    int t   = idx / (Gg * 64);
    int rem = idx - t * (Gg * 64);
    int r   = rem >> 6;
    int kk  = rem & 63;
    int k   = t * 64 + kk;
    float val = (k < Kf) ? cWih[(size_t)r * Kf + k] : cWhh[r * Hh + (k - Kf)];
    uint32_t off = sw128((uint32_t)(r * 128 + kk * 2));
    *(__half*)(g_Wq + (size_t)t * WTILE_BYTES + off) = __float2half_rn(val);
}

// ---------------------------------------------------------------------------
// Stage A (mma, single-pass fp16): per-(type, 2048-chunk) block.
// E[n]=128 matching rows -> ~2.5 64-row MMA groups (25% pad waste vs 50%
// at chunk 1024). Hn snapshot fp16 to keep 2 CTAs/SM with list[2048].
// smem: W0@0 24K | W1@24576 24K | A0@49152 8K | A1@57344 8K |
//       HN(fp16)@65536 8K | DS@73728 25600 -> 99328
// ---------------------------------------------------------------------------
constexpr int A_W0 = 0;
constexpr int A_W1 = 24576;
constexpr int A_A0 = 49152;
constexpr int A_A1 = 57344;
constexpr int A_HN = 65536;
constexpr int A_DS = 73728;
constexpr int SMEMA_BYTES = 99328;

__global__ void __launch_bounds__(256, 2)
stageA_mma(const float* __restrict__ x, const int* __restrict__ typ,
           const float* __restrict__ regs,
           const float* __restrict__ bih, const float* __restrict__ bhh)
{
    char* sm = dynsm;
    const uint32_t sb = smem_u32(sm);
    __shared__ int list[CHUNK];
    __shared__ int pcnt;

    const int tid = threadIdx.x;
    const int wid = tid >> 5, lane = tid & 31;
    const int t   = blockIdx.y;
    const int c0  = blockIdx.x * CHUNK;

    if (tid == 0) pcnt = 0;
    __syncthreads();
    for (int i = tid; i < CHUNK; i += 256) {
        if (typ[c0 + i] == t) list[atomicAdd(&pcnt, 1)] = c0 + i;
    }
    __syncthreads();
    const int n = pcnt;
    if (n == 0) return;

    {
        const unsigned char* w0 = g_WA + (size_t)(t * 2 + 0) * WTILE_BYTES;
        const unsigned char* w1 = g_WA + (size_t)(t * 2 + 1) * WTILE_BYTES;
        #pragma unroll
        for (int j = 0; j < 6; j++) {
            int i = (tid + j * 256) * 16;
            cp16(sb + A_W0 + i, w0 + i);
            cp16(sb + A_W1 + i, w1 + i);
        }
        cp_commit();
    }

    const int h  = tid & 63;
    const int rl = tid >> 6;
    const float bR  = bih[t * Gg + h]        + bhh[t * Gg + h];
    const float bZ  = bih[t * Gg + 64 + h]   + bhh[t * Gg + 64 + h];
    const float bN  = bih[t * Gg + 128 + h];
    const float bHN = bhh[t * Gg + 128 + h];

    const int arow = tid >> 2;
    const int aqd  = tid & 3;

    const int l8 = lane & 7, li = lane >> 3;
    const int am_off = (li & 1) * 8, ak_off = (li >> 1) * 8;
    const int wn_off = (li >> 1) * 8, wk_off = (li & 1) * 8;
    const int wm = wid & 1;
    const int wn = wid >> 1;

    __half* Hn = (__half*)(sm + A_HN);   // [64][64] fp16
    float*  Ds = (float*)(sm + A_DS);    // [32][200]

    bool firstGroup = true;
    for (int base = 0; base < n; base += 64) {
        const int m = (n - base < 64) ? (n - base) : 64;

        int gj = base + arow; if (gj > n - 1) gj = n - 1;
        const int gb = list[gj];

        {
            const float* rrow = regs + (size_t)gb * Kf + t * 64;
            const float* xrow = x + (size_t)gb * 64;
            float fr[16], fx[16];
            #pragma unroll
            for (int i = 0; i < 4; i++) {
                float4 vr = *(const float4*)(rrow + aqd * 16 + i * 4);
                float4 vx = *(const float4*)(xrow + aqd * 16 + i * 4);
                fr[4*i] = vr.x; fr[4*i+1] = vr.y; fr[4*i+2] = vr.z; fr[4*i+3] = vr.w;
                fx[4*i] = vx.x; fx[4*i+1] = vx.y; fx[4*i+2] = vx.z; fx[4*i+3] = vx.w;
            }
            uint32_t hr[8], hx[8];
            #pragma unroll
            for (int i = 0; i < 8; i++) {
                hr[i] = packh2(fr[2*i], fr[2*i+1]);
                hx[i] = packh2(fx[2*i], fx[2*i+1]);
            }
            uint32_t bo = (uint32_t)(arow * 128 + aqd * 32);
            uint32_t o0 = sw128(bo), o1 = sw128(bo + 16);
            *(uint4*)(sm + A_A0 + o0) = make_uint4(hr[0], hr[1], hr[2], hr[3]);
            *(uint4*)(sm + A_A0 + o1) = make_uint4(hr[4], hr[5], hr[6], hr[7]);
            *(uint4*)(sm + A_A1 + o0) = make_uint4(hx[0], hx[1], hx[2], hx[3]);
            *(uint4*)(sm + A_A1 + o1) = make_uint4(hx[4], hx[5], hx[6], hx[7]);
        }
        if (firstGroup) { cp_wait0(); firstGroup = false; }
        __syncthreads();

        float acc[2][6][4];
        #pragma unroll
        for (int a = 0; a < 2; a++)
            #pragma unroll
            for (int b = 0; b < 6; b++)
                #pragma unroll
                for (int r = 0; r < 4; r++) acc[a][b][r] = 0.0f;

        #pragma unroll
        for (int ph = 0; ph < 2; ph++) {
            const uint32_t aB = sb + (ph ? A_A1 : A_A0);
            const uint32_t wB = sb + (ph ? A_W1 : A_W0);
            #pragma unroll
            for (int ks = 0; ks < 4; ks++) {
                const int k0 = ks * 16;
                uint32_t ah[2][4];
                #pragma unroll
                for (int mt = 0; mt < 2; mt++) {
                    int row = wm * 32 + mt * 16 + am_off + l8;
                    ldsm4(ah[mt], aB + sw128((uint32_t)(row * 128 + (k0 + ak_off) * 2)));
                }
                #pragma unroll
                for (int np = 0; np < 3; np++) {
                    int nrow = wn * 48 + np * 16 + wn_off + l8;
                    uint32_t wf[4];
                    ldsm4(wf, wB + sw128((uint32_t)(nrow * 128 + (k0 + wk_off) * 2)));
                    #pragma unroll
                    for (int mt = 0; mt < 2; mt++) {
                        mma_f16(acc[mt][2*np],   ah[mt], wf);
                        mma_f16(acc[mt][2*np+1], ah[mt], wf + 2);
                    }
                }
            }
            if (ph == 0) {
                // snapshot hn = reg @ Whh_n^T (cols 128..191), fp16
                #pragma unroll
                for (int mt = 0; mt < 2; mt++)
                    #pragma unroll
                    for (int nt = 0; nt < 6; nt++) {
                        int colb = wn * 48 + nt * 8;
                        if (colb >= 128) {
                            int row0 = wm * 32 + mt * 16 + (lane >> 2);
                            int col  = colb - 128 + ((lane & 3) << 1);
                            *(uint32_t*)&Hn[row0 * 64 + col] =
                                packh2(acc[mt][nt][0], acc[mt][nt][1]);
                            *(uint32_t*)&Hn[(row0 + 8) * 64 + col] =
                                packh2(acc[mt][nt][2], acc[mt][nt][3]);
                        }
                    }
            }
        }

        #pragma unroll
        for (int half = 0; half < 2; half++) {
            __syncthreads();
            if (wm == half) {
                #pragma unroll
                for (int mt = 0; mt < 2; mt++)
                    #pragma unroll
                    for (int nt = 0; nt < 6; nt++)
                        #pragma unroll
                        for (int r = 0; r < 4; r++) {
                            int lrow = mt * 16 + (lane >> 2) + ((r >> 1) << 3);
                            int col  = wn * 48 + nt * 8 + ((lane & 3) << 1) + (r & 1);
                            Ds[lrow * 200 + col] = acc[mt][nt][r];
                        }
            }
            __syncthreads();
            #pragma unroll 2
            for (int i = 0; i < 8; i++) {
                int lrow = rl + i * 4;
                int rowg = half * 32 + lrow;
                if (rowg < m) {
                    int gbr = list[base + rowg];
                    float ar = Ds[lrow * 200 + h];
                    float az = Ds[lrow * 200 + 64 + h];
                    float an = Ds[lrow * 200 + 128 + h];
                    float hn = __half2float(Hn[rowg * 64 + h]);
                    float rg = regs[(size_t)gbr * Kf + t * 64 + h];
                    float rv = sigm(ar + bR);
                    float zv = sigm(az + bZ);
                    float nv = tanhf(an + bN + rv * bHN + (rv - 1.0f) * hn);
                    g_hidden[(size_t)gbr * 64 + h] = (1.0f - zv) * nv + zv * rg;
                }
            }
        }
        __syncthreads();
    }
}

// ---------------------------------------------------------------------------
// Stage B: single-pass fp16 mma GEMM (R11 config verbatim: M-tile 64,
// 8 warps 2m x 4n, 2 CTAs/SM, 2-stage pipeline with reg A-prefetch).
// ---------------------------------------------------------------------------
constexpr int SBUF  = 32768;
constexpr int SB_CS = 51200;
constexpr int SB_HN = 68608;
constexpr int SMEMB_BYTES = 84992;

__global__ void __launch_bounds__(256, 2)
stageB_mma(const float* __restrict__ regs, const int* __restrict__ typ,
           const float* __restrict__ c,
           const float* __restrict__ cbih, const float* __restrict__ cbhh,
           float* __restrict__ out)
{
    char* sm = dynsm;
    const uint32_t sb = smem_u32(sm);
    __shared__ int styp[64];

    const int tid  = threadIdx.x;
    const int wid  = tid >> 5, lane = tid & 31;
    const int wm   = wid & 1;
    const int wn   = wid >> 1;
    const int bm   = blockIdx.x * 64;

    if (tid < 64) styp[tid] = typ[bm + tid];
    __syncthreads();

    float acc[2][6][4];
    #pragma unroll
    for (int a = 0; a < 2; a++)
        #pragma unroll
        for (int b = 0; b < 6; b++)
            #pragma unroll
            for (int r = 0; r < 4; r++) acc[a][b][r] = 0.0f;

    const int arow = tid >> 2;
    const int aqd  = tid & 3;

    float4 pf[4];
    auto prefetchA = [&](int t) {
        const float* srow;
        if (t < Tt) {
            srow = (styp[arow] == t)
                     ? (g_hidden + (size_t)(bm + arow) * 64)
                     : (regs + (size_t)(bm + arow) * Kf + t * 64);
        } else {
            srow = c + (size_t)(bm + arow) * 64;
        }
        #pragma unroll
        for (int i = 0; i < 4; i++)
            pf[i] = *(const float4*)(srow + aqd * 16 + i * 4);
    };
    auto storeA = [&](int buf) {
        float f[16];
        #pragma unroll
        for (int i = 0; i < 4; i++) {
            f[4*i] = pf[i].x; f[4*i+1] = pf[i].y; f[4*i+2] = pf[i].z; f[4*i+3] = pf[i].w;
        }
        uint32_t hp[8];
        #pragma unroll
        for (int i = 0; i < 8; i++) hp[i] = packh2(f[2*i], f[2*i+1]);
        uint32_t bo = (uint32_t)(arow * 128 + aqd * 32);
        uint32_t o0 = sw128(bo), o1 = sw128(bo + 16);
        *(uint4*)(sm + buf * SBUF + o0) = make_uint4(hp[0], hp[1], hp[2], hp[3]);
        *(uint4*)(sm + buf * SBUF + o1) = make_uint4(hp[4], hp[5], hp[6], hp[7]);
    };
    auto loadW = [&](int t, int buf) {
        const unsigned char* src = g_Wq + (size_t)t * WTILE_BYTES;
        #pragma unroll
        for (int j = 0; j < 6; j++) {
            int i = (tid + j * 256) * 16;
            cp16(sb + buf * SBUF + 8192 + i, src + i);
        }
    };

    const int l8 = lane & 7, li = lane >> 3;
    const int am_off = (li & 1) * 8, ak_off = (li >> 1) * 8;
    const int wn_off = (li >> 1) * 8, wk_off = (li & 1) * 8;

    // prologue: tile it=0 (t=16, the c tile) into buf 0
    prefetchA(16);
    loadW(16, 0);
    cp_commit();
    storeA(0);
    prefetchA(0);
    cp_wait0();
    __syncthreads();

    for (int it = 0; it <= 16; it++) {
        const int buf = it & 1, nxt = buf ^ 1;
        if (it < 16) {
            loadW(it, nxt);
            cp_commit();
            storeA(nxt);                 // pf holds A for t = it (iteration it+1)
            if (it < 15) prefetchA(it + 1);
        }

        const uint32_t aB = sb + buf * SBUF;
        const uint32_t wB = aB + 8192;
        #pragma unroll
        for (int ks = 0; ks < 4; ks++) {
            const int k0 = ks * 16;
            uint32_t ah[2][4];
            #pragma unroll
            for (int mt = 0; mt < 2; mt++) {
                int row = wm * 32 + mt * 16 + am_off + l8;
                ldsm4(ah[mt], aB + sw128((uint32_t)(row * 128 + (k0 + ak_off) * 2)));
            }
            #pragma unroll
            for (int np = 0; np < 3; np++) {
                int nrow = wn * 48 + np * 16 + wn_off + l8;
                uint32_t wf[4];
                ldsm4(wf, wB + sw128((uint32_t)(nrow * 128 + (k0 + wk_off) * 2)));
                #pragma unroll
                for (int mt = 0; mt < 2; mt++) {
                    mma_f16(acc[mt][2*np],   ah[mt], wf);
                    mma_f16(acc[mt][2*np+1], ah[mt], wf + 2);
                }
            }
        }

        if (it == 0) {
            float* Hn = (float*)(sm + SB_HN);
            #pragma unroll
            for (int mt = 0; mt < 2; mt++)
                #pragma unroll
                for (int nt = 0; nt < 6; nt++) {
                    int colb = wn * 48 + nt * 8;
                    if (colb >= 128) {
                        #pragma unroll
                        for (int r = 0; r < 4; r++) {
                            int row = wm * 32 + mt * 16 + (lane >> 2) + ((r >> 1) << 3);
                            int col = colb - 128 + ((lane & 3) << 1) + (r & 1);
                            Hn[row * 64 + col] = acc[mt][nt][r];
                        }
                    }
                }
        }
        cp_wait0();
        __syncthreads();
    }

    // ---- epilogue ----
    float* Ds = (float*)sm;               // [64][200]
    float* cs = (float*)(sm + SB_CS);     // [64][68]
    float* Hn = (float*)(sm + SB_HN);     // [64][64]

    #pragma unroll
    for (int mt = 0; mt < 2; mt++)
        #pragma unroll
        for (int nt = 0; nt < 6; nt++)
            #pragma unroll
            for (int r = 0; r < 4; r++) {
                int row = wm * 32 + mt * 16 + (lane >> 2) + ((r >> 1) << 3);
                int col = wn * 48 + nt * 8 + ((lane & 3) << 1) + (r & 1);
                Ds[row * 200 + col] = acc[mt][nt][r];
            }
    #pragma unroll
    for (int j = 0; j < 4; j++) {
        int i   = tid + j * 256;
        int row = i >> 4, q = i & 15;
        float4 v = *(const float4*)(c + (size_t)(bm + row) * 64 + q * 4);
        *(float4*)(cs + row * 68 + q * 4) = v;
    }
    __syncthreads();

    const int h  = tid & 63;
    const int rl = tid >> 6;
    const float bR  = cbih[h]       + cbhh[h];
    const float bZ  = cbih[64 + h]  + cbhh[64 + h];
    const float bN  = cbih[128 + h];
    const float bHN = cbhh[128 + h];
    #pragma unroll 4
    for (int i = 0; i < 16; i++) {
        int row = rl + i * 4;
        float ar = Ds[row * 200 + h];
        float az = Ds[row * 200 + 64 + h];
        float an = Ds[row * 200 + 128 + h];
        float hn = Hn[row * 64 + h];
        float cv = cs[row * 68 + h];
        float rv = sigm(ar + bR);
        float zv = sigm(az + bZ);
        float nv = tanhf(an + bN + rv * bHN + (rv - 1.0f) * hn);
        out[(size_t)(bm + row) * 64 + h] = (1.0f - zv) * nv + zv * cv;
    }
}

// ---------------------------------------------------------------------------
extern "C" void kernel_launch(void* const* d_in, const int* in_sizes, int n_in,
                              void* d_out, int out_size)
{
    const float* x    = (const float*)d_in[0];
    const int*   typ  = (const int*)  d_in[1];
    const float* c    = (const float*)d_in[2];
    const float* regs = (const float*)d_in[3];
    const float* Wih  = (const float*)d_in[4];
    const float* Whh  = (const float*)d_in[5];
    const float* bih  = (const float*)d_in[6];
    const float* bhh  = (const float*)d_in[7];
    const float* cWih = (const float*)d_in[8];
    const float* cWhh = (const float*)d_in[9];
    const float* cbih = (const float*)d_in[10];
    const float* cbhh = (const float*)d_in[11];
    float* out = (float*)d_out;

    (void)in_sizes; (void)n_in; (void)out_size;

    cudaFuncSetAttribute(stageA_mma,
                         cudaFuncAttributeMaxDynamicSharedMemorySize, SMEMA_BYTES);
    cudaFuncSetAttribute(stageB_mma,
                         cudaFuncAttributeMaxDynamicSharedMemorySize, SMEMB_BYTES);

    buildA_kernel<<<(Tt * 2 * Gg * 64 + 255) / 256, 256>>>(Wih, Whh);
    stageA_mma<<<dim3(Bn / CHUNK, 16), 256, SMEMA_BYTES>>>(x, typ, regs, bih, bhh);
    buildB_kernel<<<(TILES * Gg * 64 + 255) / 256, 256>>>(cWih, cWhh);
    stageB_mma<<<Bn / 64, 256, SMEMB_BYTES>>>(regs, typ, c, cbih, cbhh, out);
}